// round 14
// baseline (speedup 1.0000x reference)
#include <cuda_runtime.h>
#include <cuda_bf16.h>
#include <math.h>
#include <stdint.h>

// Problem dims
#define T_  512
#define B_  64
#define E_  300
#define H_  512
#define L_  5
#define G3H 1536
#define M_  (T_*B_)          // 32768
#define V_  30000
#define EP_ 304              // E padded to k16 multiple

// ---------------------------------------------------------------------------
// Scratch (device globals — no runtime allocation allowed)
// ---------------------------------------------------------------------------
__device__ float g_xp0[(size_t)M_ * G3H];
__device__ float g_xp1[(size_t)M_ * G3H];
__device__ float g_h2 [(size_t)M_ * H_];
// per-producer flags: [layer][group][prod] padded 8 words (32B) apart
__device__ unsigned g_ctr2[2048];
// bf16 hi/lo split operands
__device__ unsigned short g_embh[(size_t)V_ * EP_];
__device__ unsigned short g_embl[(size_t)V_ * EP_];
__device__ unsigned short g_w0h[(size_t)G3H * EP_];
__device__ unsigned short g_w0l[(size_t)G3H * EP_];
__device__ unsigned short g_w1h[(size_t)G3H * H_];
__device__ unsigned short g_w1l[(size_t)G3H * H_];
__device__ unsigned short g_hbh[2 * (size_t)M_ * H_];
__device__ unsigned short g_hbl[2 * (size_t)M_ * H_];

// ---------------------------------------------------------------------------
// helpers
// ---------------------------------------------------------------------------
__device__ __forceinline__ unsigned ld_acquire(const unsigned* p) {
    unsigned v;
    asm volatile("ld.acquire.gpu.u32 %0, [%1];" : "=r"(v) : "l"(p) : "memory");
    return v;
}
__device__ __forceinline__ void st_release(unsigned* p, unsigned v) {
    asm volatile("st.release.gpu.global.u32 [%0], %1;" :: "l"(p), "r"(v) : "memory");
}
__device__ __forceinline__ float sigmoidf_(float x) {
    return 1.0f / (1.0f + __expf(-x));
}
__device__ __forceinline__ float tanhf_(float x) {
    return 1.0f - 2.0f / (__expf(2.0f * x) + 1.0f);
}
__device__ __forceinline__ unsigned smem_u32(const void* p) {
    unsigned a;
    asm("{ .reg .u64 t; cvta.to.shared.u64 t, %1; cvt.u32.u64 %0, t; }"
        : "=r"(a) : "l"(p));
    return a;
}
__device__ __forceinline__ unsigned bf16_bits(float x) {
    __nv_bfloat16 h = __float2bfloat16_rn(x);
    return (unsigned)(reinterpret_cast<__nv_bfloat16_raw&>(h).x);
}
__device__ __forceinline__ float bf16_val(unsigned bits) {
    __nv_bfloat16_raw r; r.x = (unsigned short)bits;
    return __bfloat162float(reinterpret_cast<__nv_bfloat16&>(r));
}
__device__ __forceinline__ void ldsm_x4(unsigned& r0, unsigned& r1,
                                        unsigned& r2, unsigned& r3, unsigned a) {
    asm volatile("ldmatrix.sync.aligned.m8n8.x4.shared.b16 {%0,%1,%2,%3},[%4];"
                 : "=r"(r0), "=r"(r1), "=r"(r2), "=r"(r3) : "r"(a));
}
__device__ __forceinline__ void mma_bf16(float& d0, float& d1, float& d2, float& d3,
                                         unsigned a0, unsigned a1, unsigned a2, unsigned a3,
                                         unsigned b0, unsigned b1) {
    asm volatile("mma.sync.aligned.m16n8k16.row.col.f32.bf16.bf16.f32 "
                 "{%0,%1,%2,%3},{%4,%5,%6,%7},{%8,%9},{%0,%1,%2,%3};"
                 : "+f"(d0), "+f"(d1), "+f"(d2), "+f"(d3)
                 : "r"(a0), "r"(a1), "r"(a2), "r"(a3), "r"(b0), "r"(b1));
}

__global__ void init_ctr_kernel() {
#pragma unroll
    for (int i = 0; i < 4; ++i)
        g_ctr2[threadIdx.x + i * 512] = 0u;
}

// ---------------------------------------------------------------------------
// Merged fp32 -> bf16 hi/lo split (emb + Wih0 + Wih1 in one launch).
// ---------------------------------------------------------------------------
__global__ void cvt_all_kernel(const float* __restrict__ emb,
                               const float* __restrict__ w0,
                               const float* __restrict__ w1) {
    const size_t N0 = (size_t)V_ * EP_;
    const size_t N1 = N0 + (size_t)G3H * EP_;
    const size_t N2 = N1 + (size_t)G3H * H_;
    for (size_t i = (size_t)blockIdx.x * blockDim.x + threadIdx.x; i < N2;
         i += (size_t)gridDim.x * blockDim.x) {
        const float* src; int ks, kd; size_t idx;
        unsigned short *dh, *dl;
        if (i < N0)      { src = emb; ks = E_; kd = EP_; idx = i;      dh = g_embh; dl = g_embl; }
        else if (i < N1) { src = w0;  ks = E_; kd = EP_; idx = i - N0; dh = g_w0h;  dl = g_w0l; }
        else             { src = w1;  ks = H_; kd = H_;  idx = i - N1; dh = g_w1h;  dl = g_w1l; }
        int r = (int)(idx / kd);
        int c = (int)(idx - (size_t)r * kd);
        float v = (c < ks) ? src[(size_t)r * ks + c] : 0.f;
        unsigned h = bf16_bits(v);
        dh[idx] = (unsigned short)h;
        dl[idx] = (unsigned short)bf16_bits(v - bf16_val(h));
    }
}

// ---------------------------------------------------------------------------
// Tensor-core projection GEMM (mma.sync, unchanged — proven)
// ---------------------------------------------------------------------------
#define PROW 24
#define PMAT 6144
#define PSTG 24576
#define SMEM_PROJ (2 * PSTG)

template <int K, int SRC>
__global__ __launch_bounds__(256, 1) void proj_mma(
    const int* __restrict__ gidx, const float* __restrict__ bias)
{
    extern __shared__ __align__(16) char smp[];
    const unsigned short* Ah = (SRC == 0) ? g_embh : g_hbh;
    const unsigned short* Al = (SRC == 0) ? g_embl : g_hbl;
    const unsigned short* Wh = (SRC == 0) ? g_w0h : g_w1h;
    const unsigned short* Wl = (SRC == 0) ? g_w0l : g_w1l;
    float* C = (SRC == 0) ? g_xp0 : g_xp1;

    const int tid = threadIdx.x;
    const int li  = tid & 31;
    const int w   = tid >> 5;
    const int wm  = w >> 1;
    const int wn  = w & 1;
    const int m0  = blockIdx.y * 128;
    const int n0  = blockIdx.x * 128;
    const unsigned sbase = smem_u32(smp);

    const int lrow  = tid >> 1;
    const int lhalf = tid & 1;
    size_t arow;
    if (SRC == 0) arow = (size_t)__ldg(gidx + m0 + lrow) * K;
    else          arow = (size_t)(m0 + lrow) * K;
    const size_t brow = (size_t)(n0 + lrow) * K;
    const unsigned sst = (unsigned)(lrow * PROW + lhalf * 8) * 2;

    float acc[2][8][4];
#pragma unroll
    for (int a = 0; a < 2; ++a)
#pragma unroll
        for (int b = 0; b < 8; ++b)
#pragma unroll
            for (int c = 0; c < 4; ++c) acc[a][b][c] = 0.f;

    const int KT = K / 16;
    uint4 rAh, rAl, rBh, rBl;
    {
        const int k0 = lhalf * 8;
        rAh = *(const uint4*)(Ah + arow + k0);
        rAl = *(const uint4*)(Al + arow + k0);
        rBh = *(const uint4*)(Wh + brow + k0);
        rBl = *(const uint4*)(Wl + brow + k0);
        *(uint4*)(smp + 0 * PMAT + sst) = rAh;
        *(uint4*)(smp + 1 * PMAT + sst) = rAl;
        *(uint4*)(smp + 2 * PMAT + sst) = rBh;
        *(uint4*)(smp + 3 * PMAT + sst) = rBl;
    }
    __syncthreads();

    const unsigned aoff = (unsigned)((wm * 32 + (li & 15)) * PROW + (li >> 4) * 8) * 2;
    const unsigned boff = (unsigned)((wn * 64 + (li & 15)) * PROW + (li >> 4) * 8) * 2;

    for (int kt = 0; kt < KT; ++kt) {
        const unsigned sb0 = sbase + (unsigned)(kt & 1) * PSTG;
        if (kt + 1 < KT) {
            const int k0 = (kt + 1) * 16 + lhalf * 8;
            rAh = *(const uint4*)(Ah + arow + k0);
            rAl = *(const uint4*)(Al + arow + k0);
            rBh = *(const uint4*)(Wh + brow + k0);
            rBl = *(const uint4*)(Wl + brow + k0);
        }

        unsigned aH[2][4], aL[2][4];
#pragma unroll
        for (int mt = 0; mt < 2; ++mt) {
            ldsm_x4(aH[mt][0], aH[mt][1], aH[mt][2], aH[mt][3],
                    sb0 + 0 * PMAT + aoff + mt * 768);
            ldsm_x4(aL[mt][0], aL[mt][1], aL[mt][2], aL[mt][3],
                    sb0 + 1 * PMAT + aoff + mt * 768);
        }
#pragma unroll
        for (int ng = 0; ng < 4; ++ng) {
            unsigned bh[4], bl[4];
            ldsm_x4(bh[0], bh[1], bh[2], bh[3], sb0 + 2 * PMAT + boff + ng * 768);
            ldsm_x4(bl[0], bl[1], bl[2], bl[3], sb0 + 3 * PMAT + boff + ng * 768);
#pragma unroll
            for (int mt = 0; mt < 2; ++mt) {
                float* d0 = acc[mt][2 * ng];
                mma_bf16(d0[0], d0[1], d0[2], d0[3],
                         aH[mt][0], aH[mt][1], aH[mt][2], aH[mt][3], bh[0], bh[2]);
                mma_bf16(d0[0], d0[1], d0[2], d0[3],
                         aH[mt][0], aH[mt][1], aH[mt][2], aH[mt][3], bl[0], bl[2]);
                mma_bf16(d0[0], d0[1], d0[2], d0[3],
                         aL[mt][0], aL[mt][1], aL[mt][2], aL[mt][3], bh[0], bh[2]);
                float* d1 = acc[mt][2 * ng + 1];
                mma_bf16(d1[0], d1[1], d1[2], d1[3],
                         aH[mt][0], aH[mt][1], aH[mt][2], aH[mt][3], bh[1], bh[3]);
                mma_bf16(d1[0], d1[1], d1[2], d1[3],
                         aH[mt][0], aH[mt][1], aH[mt][2], aH[mt][3], bl[1], bl[3]);
                mma_bf16(d1[0], d1[1], d1[2], d1[3],
                         aL[mt][0], aL[mt][1], aL[mt][2], aL[mt][3], bh[1], bh[3]);
            }
        }
        if (kt + 1 < KT) {
            char* nb = smp + ((kt & 1) ^ 1) * PSTG;
            *(uint4*)(nb + 0 * PMAT + sst) = rAh;
            *(uint4*)(nb + 1 * PMAT + sst) = rAl;
            *(uint4*)(nb + 2 * PMAT + sst) = rBh;
            *(uint4*)(nb + 3 * PMAT + sst) = rBl;
            __syncthreads();
        }
    }

    const int fg = li >> 2;
    const int ft = li & 3;
#pragma unroll
    for (int mt = 0; mt < 2; ++mt) {
#pragma unroll
        for (int nt = 0; nt < 8; ++nt) {
            const int row = m0 + wm * 32 + mt * 16 + fg;
            const int col = n0 + wn * 64 + nt * 8 + 2 * ft;
            const float b0 = __ldg(bias + col);
            const float b1 = __ldg(bias + col + 1);
            float* c0 = C + (size_t)row * G3H + col;
            float* c1 = C + (size_t)(row + 8) * G3H + col;
            *(float2*)c0 = make_float2(acc[mt][nt][0] + b0, acc[mt][nt][1] + b1);
            *(float2*)c1 = make_float2(acc[mt][nt][2] + b0, acc[mt][nt][3] + b1);
        }
    }
}

// ---------------------------------------------------------------------------
// Persistent GRU recurrence — R13 core + de-contended handshake:
//  * per-producer flags (st.release), no shared counter atomic
//  * each warp: lanes 0-7 poll the 8 producers of its own k-half in parallel
//  * per-half staging + named half-barriers (bar 2/3, 192 threads) so each
//    k-half's LDSM/HMMA starts as soon as its own producers arrive
// ---------------------------------------------------------------------------
#define WROW    520
#define WH_OFF  0
#define WL_OFF  99840
#define HH_OFF  199680
#define HL_OFF  208000
#define RED_OFF 216320
#define SB_OFF  223232
#define SMEM_REC_BYTES 223616

__global__ __launch_bounds__(384, 1) void rec_kernel(
    const float* __restrict__ Whh, const float* __restrict__ bhh, int layer)
{
    extern __shared__ char smc[];
    float* red = (float*)(smc + RED_OFF);
    float* sb  = (float*)(smc + SB_OFF);
    const unsigned sbase = smem_u32(smc);

    const float* xp = layer ? g_xp1 : g_xp0;

    const int tid   = threadIdx.x;
    const int wid   = tid >> 5;
    const int li    = tid & 31;
    const int bid   = blockIdx.x;
    const int group = bid >> 4;
    const int gidx  = bid & 15;
    const int rb    = group * 8;
    const int ibase = gidx * 32;

    unsigned* flags  = g_ctr2 + (layer * 8 + group) * 128;   // 16 producers x 8 words
    unsigned* myflag = flags + gidx * 8;

    unsigned short* hbh = g_hbh + (size_t)layer * M_ * H_;
    unsigned short* hbl = g_hbl + (size_t)layer * M_ * H_;

    // ---- preload weights (bf16 hi/lo split) + bias ----
    for (int idx = tid; idx < 96 * 256; idx += 384) {
        int r  = idx >> 8;
        int kk = (idx & 255) << 1;
        int gr = (r >> 5) * 512 + ibase + (r & 31);
        float2 wv = *(const float2*)(Whh + (size_t)gr * 512 + kk);
        unsigned h0 = bf16_bits(wv.x), h1 = bf16_bits(wv.y);
        unsigned l0 = bf16_bits(wv.x - bf16_val(h0));
        unsigned l1 = bf16_bits(wv.y - bf16_val(h1));
        *(unsigned*)(smc + WH_OFF + (r * WROW + kk) * 2) = (h1 << 16) | h0;
        *(unsigned*)(smc + WL_OFF + (r * WROW + kk) * 2) = (l1 << 16) | l0;
    }
    if (tid < 96) {
        int gr = (tid >> 5) * 512 + ibase + (tid & 31);
        sb[tid] = __ldg(bhh + gr);
    }
    __syncthreads();

    // MMA warp roles
    const int mt = wid % 6;
    const int kh = wid / 6;                // 0: warps 0-5 (tid 0-191), 1: warps 6-11
    const int k0 = kh * 256;
    const int la = li & 15;
    const unsigned aoff = ((mt * 16 + la) * WROW + k0 + ((li >> 4) & 1) * 8) * 2;
    const unsigned aAhi = sbase + WH_OFF + aoff;
    const unsigned aAlo = sbase + WL_OFF + aoff;
    const unsigned boff4 = (((li & 7) * WROW) + k0 + ((li >> 3) & 3) * 8) * 2;
    const unsigned aBhi = sbase + HH_OFF + boff4;
    const unsigned aBlo = sbase + HL_OFF + boff4;
    const int fg = li >> 2;
    const int ft = li & 3;
    const int eb = tid >> 5;
    const int ei = tid & 31;
    const int ht = tid - kh * 192;         // thread id within half-group (0..191)
    const int barid = 2 + kh;

    // ---- A-hi fragments: register-resident for the whole kernel ----
    unsigned aH[16][4];
#pragma unroll
    for (int ks = 0; ks < 16; ++ks)
        ldsm_x4(aH[ks][0], aH[ks][1], aH[ks][2], aH[ks][3], aAhi + ks * 32);

    float h_prev_reg = 0.f;

    for (int t = 0; t < T_; ++t) {
        // ---- xp prefetch (overlaps poll) ----
        float xr = 0.f, xz = 0.f, xn = 0.f;
        if (tid < 256) {
            const float* xrow = xp + ((size_t)t * B_ + rb + eb) * G3H + ibase + ei;
            xr = __ldg(xrow);
            xz = __ldg(xrow + 512);
            xn = __ldg(xrow + 1024);
        }

        // ---- parallel per-producer poll + half-local staging ----
        if (t == 0) {
            for (int idx = ht; idx < 1024; idx += 192) {
                int plane = idx >> 9;
                int rem   = idx & 511;
                int b  = rem >> 6;
                int kk = k0 + ((rem & 63) << 2);
                *(unsigned long long*)(smc + (plane ? HL_OFF : HH_OFF)
                                       + (b * WROW + kk) * 2) = 0ull;
            }
        } else {
            if (li < 8) {
                const unsigned* f = flags + (kh * 8 + li) * 8;
                while (ld_acquire(f) < (unsigned)t) { }
            }
            __syncwarp();
            const size_t base = ((size_t)(t - 1) * B_ + rb) * H_;
            for (int idx = ht; idx < 1024; idx += 192) {
                int plane = idx >> 9;
                int rem   = idx & 511;
                int b  = rem >> 6;
                int kk = k0 + ((rem & 63) << 2);
                const unsigned short* src = plane ? hbl : hbh;
                unsigned long long v = __ldcg(
                    (const unsigned long long*)(src + base + (size_t)b * H_ + kk));
                *(unsigned long long*)(smc + (plane ? HL_OFF : HH_OFF)
                                       + (b * WROW + kk) * 2) = v;
            }
        }
        asm volatile("bar.sync %0, 192;" :: "r"(barid) : "memory");

        // ---- tensor-core matvec: all 12 warps; even/odd ps chains split ----
        {
            float d0e[4] = {0.f, 0.f, 0.f, 0.f};
            float d0o[4] = {0.f, 0.f, 0.f, 0.f};
            float d1e[4] = {0.f, 0.f, 0.f, 0.f};
            float d1o[4] = {0.f, 0.f, 0.f, 0.f};
#pragma unroll
            for (int ps = 0; ps < 8; ++ps) {
                const unsigned pb = ps * 64;
                unsigned bh[4], bl[4], al0[4], al1[4];
                ldsm_x4(bh[0], bh[1], bh[2], bh[3], aBhi + pb);
                ldsm_x4(bl[0], bl[1], bl[2], bl[3], aBlo + pb);
                ldsm_x4(al0[0], al0[1], al0[2], al0[3], aAlo + (2 * ps) * 32);
                ldsm_x4(al1[0], al1[1], al1[2], al1[3], aAlo + (2 * ps + 1) * 32);
                const unsigned* a0 = aH[2 * ps];
                const unsigned* a1 = aH[2 * ps + 1];
                float* d0 = (ps & 1) ? d0o : d0e;
                float* d1 = (ps & 1) ? d1o : d1e;
                mma_bf16(d0[0], d0[1], d0[2], d0[3],
                         a0[0], a0[1], a0[2], a0[3], bh[0], bh[1]);
                mma_bf16(d0[0], d0[1], d0[2], d0[3],
                         a0[0], a0[1], a0[2], a0[3], bl[0], bl[1]);
                mma_bf16(d0[0], d0[1], d0[2], d0[3],
                         al0[0], al0[1], al0[2], al0[3], bh[0], bh[1]);
                mma_bf16(d1[0], d1[1], d1[2], d1[3],
                         a1[0], a1[1], a1[2], a1[3], bh[2], bh[3]);
                mma_bf16(d1[0], d1[1], d1[2], d1[3],
                         a1[0], a1[1], a1[2], a1[3], bl[2], bl[3]);
                mma_bf16(d1[0], d1[1], d1[2], d1[3],
                         al1[0], al1[1], al1[2], al1[3], bh[2], bh[3]);
            }
            float* rk = red + kh * 96 * 9;
            rk[(mt * 16 + fg)     * 9 + 2 * ft    ] = d0e[0] + d1e[0] + d0o[0] + d1o[0];
            rk[(mt * 16 + fg)     * 9 + 2 * ft + 1] = d0e[1] + d1e[1] + d0o[1] + d1o[1];
            rk[(mt * 16 + fg + 8) * 9 + 2 * ft    ] = d0e[2] + d1e[2] + d0o[2] + d1o[2];
            rk[(mt * 16 + fg + 8) * 9 + 2 * ft + 1] = d0e[3] + d1e[3] + d0o[3] + d1o[3];
        }
        __syncthreads();

        // ---- elementwise (threads 0-255) + early release ----
        if (tid < 256) {
            float ghr = red[(ei) * 9 + eb]      + red[96 * 9 + (ei) * 9 + eb];
            float ghz = red[(32 + ei) * 9 + eb] + red[96 * 9 + (32 + ei) * 9 + eb];
            float ghn = red[(64 + ei) * 9 + eb] + red[96 * 9 + (64 + ei) * 9 + eb];
            ghr += sb[ei];
            ghz += sb[32 + ei];
            ghn += sb[64 + ei];

            float r = sigmoidf_(xr + ghr);
            float z = sigmoidf_(xz + ghz);
            float n = tanhf_(xn + r * ghn);
            float hnew = n + z * (h_prev_reg - n);
            h_prev_reg = hnew;

            const size_t off = ((size_t)t * B_ + rb + eb) * H_ + ibase + ei;
            unsigned hb = bf16_bits(hnew);
            float rem = hnew - bf16_val(hb);
            hbh[off] = (unsigned short)hb;
            hbl[off] = (unsigned short)bf16_bits(rem);
            if (layer) __stcg(g_h2 + off, hnew);

            asm volatile("bar.sync 1, 256;" ::: "memory");
            if (tid == 0) st_release(myflag, (unsigned)(t + 1));
        }
        // MMA-only warps (8-11) proceed to next-step poll/staging; they block
        // on the per-producer flags (which include own CTA only if gidx>=8 —
        // cross-step smem hazards are gated by bar1 ordering through red/HH).
    }
}

// ---------------------------------------------------------------------------
// Pool over batch + FC
// ---------------------------------------------------------------------------
__global__ __launch_bounds__(256) void pool_fc_kernel(
    const float* __restrict__ fcW, const float* __restrict__ fcb,
    float* __restrict__ out)
{
    __shared__ float rbuf[5][256];
    const int t = blockIdx.x;
    const int tid = threadIdx.x;

    float s0 = 0.f, s1 = 0.f;
    const float* base = g_h2 + (size_t)t * B_ * H_ + tid * 2;
#pragma unroll 8
    for (int b = 0; b < B_; ++b) {
        float2 vv = *(const float2*)(base + (size_t)b * H_);
        s0 += vv.x; s1 += vv.y;
    }
    s0 *= (1.0f / 64.0f);
    s1 *= (1.0f / 64.0f);

#pragma unroll
    for (int l = 0; l < L_; ++l)
        rbuf[l][tid] = s0 * __ldg(fcW + l * H_ + tid * 2)
                     + s1 * __ldg(fcW + l * H_ + tid * 2 + 1);
    __syncthreads();

    for (int s = 128; s > 0; s >>= 1) {
        if (tid < s) {
#pragma unroll
            for (int l = 0; l < L_; ++l) rbuf[l][tid] += rbuf[l][tid + s];
        }
        __syncthreads();
    }
    if (tid < L_) out[t * L_ + tid] = rbuf[tid][0] + __ldg(fcb + tid);
}

// ---------------------------------------------------------------------------
// launcher
// ---------------------------------------------------------------------------
extern "C" void kernel_launch(void* const* d_in, const int* in_sizes, int n_in,
                              void* d_out, int out_size) {
    (void)in_sizes; (void)n_in; (void)out_size;
    const int*   texts = (const int*)  d_in[0];
    const float* emb   = (const float*)d_in[1];
    const float* Wih0  = (const float*)d_in[2];
    const float* Whh0  = (const float*)d_in[3];
    const float* bih0  = (const float*)d_in[4];
    const float* bhh0  = (const float*)d_in[5];
    const float* Wih1  = (const float*)d_in[6];
    const float* Whh1  = (const float*)d_in[7];
    const float* bih1  = (const float*)d_in[8];
    const float* bhh1  = (const float*)d_in[9];
    const float* fcW   = (const float*)d_in[10];
    const float* fcb   = (const float*)d_in[11];
    float* out = (float*)d_out;

    cudaFuncSetAttribute(rec_kernel,
                         cudaFuncAttributeMaxDynamicSharedMemorySize,
                         SMEM_REC_BYTES);
    cudaFuncSetAttribute(proj_mma<EP_, 0>,
                         cudaFuncAttributeMaxDynamicSharedMemorySize, SMEM_PROJ);
    cudaFuncSetAttribute(proj_mma<H_, 1>,
                         cudaFuncAttributeMaxDynamicSharedMemorySize, SMEM_PROJ);

    init_ctr_kernel<<<1, 512>>>();
    cvt_all_kernel<<<4096, 256>>>(emb, Wih0, Wih1);
    proj_mma<EP_, 0><<<dim3(12, 256), 256, SMEM_PROJ>>>(texts, bih0);
    rec_kernel<<<128, 384, SMEM_REC_BYTES>>>(Whh0, bhh0, 0);
    proj_mma<H_, 1><<<dim3(12, 256), 256, SMEM_PROJ>>>(nullptr, bih1);
    rec_kernel<<<128, 384, SMEM_REC_BYTES>>>(Whh1, bhh1, 1);
    pool_fc_kernel<<<512, 256>>>(fcW, fcb, out);
}

// round 15
// speedup vs baseline: 1.4055x; 1.4055x over previous
#include <cuda_runtime.h>
#include <cuda_bf16.h>
#include <math.h>
#include <stdint.h>

// Problem dims
#define T_  512
#define B_  64
#define E_  300
#define H_  512
#define L_  5
#define G3H 1536
#define M_  (T_*B_)          // 32768
#define V_  30000
#define EP_ 304              // E padded to k16 multiple

// ---------------------------------------------------------------------------
// Scratch (device globals — no runtime allocation allowed)
// ---------------------------------------------------------------------------
__device__ float g_xp0[(size_t)M_ * G3H];
__device__ float g_xp1[(size_t)M_ * G3H];
__device__ float g_h2 [(size_t)M_ * H_];
__device__ unsigned g_ctr2[2048];
// bf16 hi/lo split operands
__device__ unsigned short g_embh[(size_t)V_ * EP_];
__device__ unsigned short g_embl[(size_t)V_ * EP_];
__device__ unsigned short g_w0h[(size_t)G3H * EP_];
__device__ unsigned short g_w0l[(size_t)G3H * EP_];
__device__ unsigned short g_w1h[(size_t)G3H * H_];
__device__ unsigned short g_w1l[(size_t)G3H * H_];
__device__ unsigned short g_hbh[2 * (size_t)M_ * H_];
__device__ unsigned short g_hbl[2 * (size_t)M_ * H_];

// ---------------------------------------------------------------------------
// helpers
// ---------------------------------------------------------------------------
__device__ __forceinline__ unsigned ld_acquire(const unsigned* p) {
    unsigned v;
    asm volatile("ld.acquire.gpu.u32 %0, [%1];" : "=r"(v) : "l"(p) : "memory");
    return v;
}
__device__ __forceinline__ void red_release(unsigned* p, unsigned v) {
    asm volatile("red.release.gpu.global.add.u32 [%0], %1;" :: "l"(p), "r"(v) : "memory");
}
__device__ __forceinline__ float sigmoidf_(float x) {
    return 1.0f / (1.0f + __expf(-x));
}
__device__ __forceinline__ float tanhf_(float x) {
    return 1.0f - 2.0f / (__expf(2.0f * x) + 1.0f);
}
__device__ __forceinline__ unsigned smem_u32(const void* p) {
    unsigned a;
    asm("{ .reg .u64 t; cvta.to.shared.u64 t, %1; cvt.u32.u64 %0, t; }"
        : "=r"(a) : "l"(p));
    return a;
}
__device__ __forceinline__ unsigned bf16_bits(float x) {
    __nv_bfloat16 h = __float2bfloat16_rn(x);
    return (unsigned)(reinterpret_cast<__nv_bfloat16_raw&>(h).x);
}
__device__ __forceinline__ float bf16_val(unsigned bits) {
    __nv_bfloat16_raw r; r.x = (unsigned short)bits;
    return __bfloat162float(reinterpret_cast<__nv_bfloat16&>(r));
}
__device__ __forceinline__ void ldsm_x4(unsigned& r0, unsigned& r1,
                                        unsigned& r2, unsigned& r3, unsigned a) {
    asm volatile("ldmatrix.sync.aligned.m8n8.x4.shared.b16 {%0,%1,%2,%3},[%4];"
                 : "=r"(r0), "=r"(r1), "=r"(r2), "=r"(r3) : "r"(a));
}
__device__ __forceinline__ void mma_bf16(float& d0, float& d1, float& d2, float& d3,
                                         unsigned a0, unsigned a1, unsigned a2, unsigned a3,
                                         unsigned b0, unsigned b1) {
    asm volatile("mma.sync.aligned.m16n8k16.row.col.f32.bf16.bf16.f32 "
                 "{%0,%1,%2,%3},{%4,%5,%6,%7},{%8,%9},{%0,%1,%2,%3};"
                 : "+f"(d0), "+f"(d1), "+f"(d2), "+f"(d3)
                 : "r"(a0), "r"(a1), "r"(a2), "r"(a3), "r"(b0), "r"(b1));
}

__global__ void init_ctr_kernel() {
#pragma unroll
    for (int i = 0; i < 4; ++i)
        g_ctr2[threadIdx.x + i * 512] = 0u;
}

// no-op: steers the ncu capture ordinal onto proj_mma<EP_,0> this round
__global__ void noop_kernel() {}

// ---------------------------------------------------------------------------
// Merged fp32 -> bf16 hi/lo split (emb + Wih0 + Wih1 in one launch).
// ---------------------------------------------------------------------------
__global__ void cvt_all_kernel(const float* __restrict__ emb,
                               const float* __restrict__ w0,
                               const float* __restrict__ w1) {
    const size_t N0 = (size_t)V_ * EP_;
    const size_t N1 = N0 + (size_t)G3H * EP_;
    const size_t N2 = N1 + (size_t)G3H * H_;
    for (size_t i = (size_t)blockIdx.x * blockDim.x + threadIdx.x; i < N2;
         i += (size_t)gridDim.x * blockDim.x) {
        const float* src; int ks, kd; size_t idx;
        unsigned short *dh, *dl;
        if (i < N0)      { src = emb; ks = E_; kd = EP_; idx = i;      dh = g_embh; dl = g_embl; }
        else if (i < N1) { src = w0;  ks = E_; kd = EP_; idx = i - N0; dh = g_w0h;  dl = g_w0l; }
        else             { src = w1;  ks = H_; kd = H_;  idx = i - N1; dh = g_w1h;  dl = g_w1l; }
        int r = (int)(idx / kd);
        int c = (int)(idx - (size_t)r * kd);
        float v = (c < ks) ? src[(size_t)r * ks + c] : 0.f;
        unsigned h = bf16_bits(v);
        dh[idx] = (unsigned short)h;
        dl[idx] = (unsigned short)bf16_bits(v - bf16_val(h));
    }
}

// ---------------------------------------------------------------------------
// Tensor-core projection GEMM (mma.sync) — now __launch_bounds__(256, 2):
// forces the 128-reg budget so 2 CTAs co-reside per SM (48KB smem each).
// ---------------------------------------------------------------------------
#define PROW 24
#define PMAT 6144
#define PSTG 24576
#define SMEM_PROJ (2 * PSTG)

template <int K, int SRC>
__global__ __launch_bounds__(256, 2) void proj_mma(
    const int* __restrict__ gidx, const float* __restrict__ bias)
{
    extern __shared__ __align__(16) char smp[];
    const unsigned short* Ah = (SRC == 0) ? g_embh : g_hbh;
    const unsigned short* Al = (SRC == 0) ? g_embl : g_hbl;
    const unsigned short* Wh = (SRC == 0) ? g_w0h : g_w1h;
    const unsigned short* Wl = (SRC == 0) ? g_w0l : g_w1l;
    float* C = (SRC == 0) ? g_xp0 : g_xp1;

    const int tid = threadIdx.x;
    const int li  = tid & 31;
    const int w   = tid >> 5;
    const int wm  = w >> 1;
    const int wn  = w & 1;
    const int m0  = blockIdx.y * 128;
    const int n0  = blockIdx.x * 128;
    const unsigned sbase = smem_u32(smp);

    const int lrow  = tid >> 1;
    const int lhalf = tid & 1;
    size_t arow;
    if (SRC == 0) arow = (size_t)__ldg(gidx + m0 + lrow) * K;
    else          arow = (size_t)(m0 + lrow) * K;
    const size_t brow = (size_t)(n0 + lrow) * K;
    const unsigned sst = (unsigned)(lrow * PROW + lhalf * 8) * 2;

    float acc[2][8][4];
#pragma unroll
    for (int a = 0; a < 2; ++a)
#pragma unroll
        for (int b = 0; b < 8; ++b)
#pragma unroll
            for (int c = 0; c < 4; ++c) acc[a][b][c] = 0.f;

    const int KT = K / 16;
    uint4 rAh, rAl, rBh, rBl;
    {
        const int k0 = lhalf * 8;
        rAh = *(const uint4*)(Ah + arow + k0);
        rAl = *(const uint4*)(Al + arow + k0);
        rBh = *(const uint4*)(Wh + brow + k0);
        rBl = *(const uint4*)(Wl + brow + k0);
        *(uint4*)(smp + 0 * PMAT + sst) = rAh;
        *(uint4*)(smp + 1 * PMAT + sst) = rAl;
        *(uint4*)(smp + 2 * PMAT + sst) = rBh;
        *(uint4*)(smp + 3 * PMAT + sst) = rBl;
    }
    __syncthreads();

    const unsigned aoff = (unsigned)((wm * 32 + (li & 15)) * PROW + (li >> 4) * 8) * 2;
    const unsigned boff = (unsigned)((wn * 64 + (li & 15)) * PROW + (li >> 4) * 8) * 2;

    for (int kt = 0; kt < KT; ++kt) {
        const unsigned sb0 = sbase + (unsigned)(kt & 1) * PSTG;
        if (kt + 1 < KT) {
            const int k0 = (kt + 1) * 16 + lhalf * 8;
            rAh = *(const uint4*)(Ah + arow + k0);
            rAl = *(const uint4*)(Al + arow + k0);
            rBh = *(const uint4*)(Wh + brow + k0);
            rBl = *(const uint4*)(Wl + brow + k0);
        }

        unsigned aH[2][4], aL[2][4];
#pragma unroll
        for (int mt = 0; mt < 2; ++mt) {
            ldsm_x4(aH[mt][0], aH[mt][1], aH[mt][2], aH[mt][3],
                    sb0 + 0 * PMAT + aoff + mt * 768);
            ldsm_x4(aL[mt][0], aL[mt][1], aL[mt][2], aL[mt][3],
                    sb0 + 1 * PMAT + aoff + mt * 768);
        }
#pragma unroll
        for (int ng = 0; ng < 4; ++ng) {
            unsigned bh[4], bl[4];
            ldsm_x4(bh[0], bh[1], bh[2], bh[3], sb0 + 2 * PMAT + boff + ng * 768);
            ldsm_x4(bl[0], bl[1], bl[2], bl[3], sb0 + 3 * PMAT + boff + ng * 768);
#pragma unroll
            for (int mt = 0; mt < 2; ++mt) {
                float* d0 = acc[mt][2 * ng];
                mma_bf16(d0[0], d0[1], d0[2], d0[3],
                         aH[mt][0], aH[mt][1], aH[mt][2], aH[mt][3], bh[0], bh[2]);
                mma_bf16(d0[0], d0[1], d0[2], d0[3],
                         aH[mt][0], aH[mt][1], aH[mt][2], aH[mt][3], bl[0], bl[2]);
                mma_bf16(d0[0], d0[1], d0[2], d0[3],
                         aL[mt][0], aL[mt][1], aL[mt][2], aL[mt][3], bh[0], bh[2]);
                float* d1 = acc[mt][2 * ng + 1];
                mma_bf16(d1[0], d1[1], d1[2], d1[3],
                         aH[mt][0], aH[mt][1], aH[mt][2], aH[mt][3], bh[1], bh[3]);
                mma_bf16(d1[0], d1[1], d1[2], d1[3],
                         aH[mt][0], aH[mt][1], aH[mt][2], aH[mt][3], bl[1], bl[3]);
                mma_bf16(d1[0], d1[1], d1[2], d1[3],
                         aL[mt][0], aL[mt][1], aL[mt][2], aL[mt][3], bh[1], bh[3]);
            }
        }
        if (kt + 1 < KT) {
            char* nb = smp + ((kt & 1) ^ 1) * PSTG;
            *(uint4*)(nb + 0 * PMAT + sst) = rAh;
            *(uint4*)(nb + 1 * PMAT + sst) = rAl;
            *(uint4*)(nb + 2 * PMAT + sst) = rBh;
            *(uint4*)(nb + 3 * PMAT + sst) = rBl;
            __syncthreads();
        }
    }

    const int fg = li >> 2;
    const int ft = li & 3;
#pragma unroll
    for (int mt = 0; mt < 2; ++mt) {
#pragma unroll
        for (int nt = 0; nt < 8; ++nt) {
            const int row = m0 + wm * 32 + mt * 16 + fg;
            const int col = n0 + wn * 64 + nt * 8 + 2 * ft;
            const float b0 = __ldg(bias + col);
            const float b1 = __ldg(bias + col + 1);
            float* c0 = C + (size_t)row * G3H + col;
            float* c1 = C + (size_t)(row + 8) * G3H + col;
            *(float2*)c0 = make_float2(acc[mt][nt][0] + b0, acc[mt][nt][1] + b1);
            *(float2*)c1 = make_float2(acc[mt][nt][2] + b0, acc[mt][nt][3] + b1);
        }
    }
}

// ---------------------------------------------------------------------------
// Persistent GRU recurrence — R11 kernel VERBATIM (proven 4149 us).
// ---------------------------------------------------------------------------
#define WROW    520
#define WH_OFF  0
#define WL_OFF  99840
#define HH_OFF  199680
#define HL_OFF  208000
#define RED_OFF 216320
#define SB_OFF  223232
#define SMEM_REC_BYTES 223616

__global__ __launch_bounds__(384, 1) void rec_kernel(
    const float* __restrict__ Whh, const float* __restrict__ bhh, int layer)
{
    extern __shared__ char smc[];
    float* red = (float*)(smc + RED_OFF);
    float* sb  = (float*)(smc + SB_OFF);
    const unsigned sbase = smem_u32(smc);

    const float* xp = layer ? g_xp1 : g_xp0;

    const int tid   = threadIdx.x;
    const int wid   = tid >> 5;
    const int li    = tid & 31;
    const int bid   = blockIdx.x;
    const int group = bid >> 4;
    const int gidx  = bid & 15;
    const int rb    = group * 8;
    const int ibase = gidx * 32;
    unsigned* ctr = g_ctr2 + (layer * 8 + group) * 32;

    unsigned short* hbh = g_hbh + (size_t)layer * M_ * H_;
    unsigned short* hbl = g_hbl + (size_t)layer * M_ * H_;

    // ---- preload weights (bf16 hi/lo split) + bias ----
    for (int idx = tid; idx < 96 * 256; idx += 384) {
        int r  = idx >> 8;
        int kk = (idx & 255) << 1;
        int gr = (r >> 5) * 512 + ibase + (r & 31);
        float2 wv = *(const float2*)(Whh + (size_t)gr * 512 + kk);
        unsigned h0 = bf16_bits(wv.x), h1 = bf16_bits(wv.y);
        unsigned l0 = bf16_bits(wv.x - bf16_val(h0));
        unsigned l1 = bf16_bits(wv.y - bf16_val(h1));
        *(unsigned*)(smc + WH_OFF + (r * WROW + kk) * 2) = (h1 << 16) | h0;
        *(unsigned*)(smc + WL_OFF + (r * WROW + kk) * 2) = (l1 << 16) | l0;
    }
    if (tid < 96) {
        int gr = (tid >> 5) * 512 + ibase + (tid & 31);
        sb[tid] = __ldg(bhh + gr);
    }
    __syncthreads();

    // MMA warp roles
    const int mt = wid % 6;
    const int kh = wid / 6;
    const int k0 = kh * 256;
    const int la = li & 15;
    const unsigned aoff = ((mt * 16 + la) * WROW + k0 + ((li >> 4) & 1) * 8) * 2;
    const unsigned aAhi = sbase + WH_OFF + aoff;
    const unsigned aAlo = sbase + WL_OFF + aoff;
    const unsigned boff4 = (((li & 7) * WROW) + k0 + ((li >> 3) & 3) * 8) * 2;
    const unsigned aBhi = sbase + HH_OFF + boff4;
    const unsigned aBlo = sbase + HL_OFF + boff4;
    const int fg = li >> 2;
    const int ft = li & 3;
    const int eb = tid >> 5;
    const int ei = tid & 31;

    // ---- A-hi fragments: register-resident for the whole kernel ----
    unsigned aH[16][4];
#pragma unroll
    for (int ks = 0; ks < 16; ++ks)
        ldsm_x4(aH[ks][0], aH[ks][1], aH[ks][2], aH[ks][3], aAhi + ks * 32);

    float h_prev_reg = 0.f;

    for (int t = 0; t < T_; ++t) {
        // ---- xp prefetch (overlaps poll) ----
        float xr = 0.f, xz = 0.f, xn = 0.f;
        if (tid < 256) {
            const float* xrow = xp + ((size_t)t * B_ + rb + eb) * G3H + ibase + ei;
            xr = __ldg(xrow);
            xz = __ldg(xrow + 512);
            xn = __ldg(xrow + 1024);
        }

        // ---- per-warp poll + u64 staging ----
        if (t == 0) {
            for (int idx = tid; idx < 2048; idx += 384) {
                int b = idx >> 8, kk = (idx & 255) << 1;
                *(unsigned*)(smc + HH_OFF + (b * WROW + kk) * 2) = 0u;
                *(unsigned*)(smc + HL_OFF + (b * WROW + kk) * 2) = 0u;
            }
        } else {
            if (li == 0) {
                unsigned target = 16u * (unsigned)t;
                while (ld_acquire(ctr) < target) { }
            }
            __syncwarp();
            const size_t base = ((size_t)(t - 1) * B_ + rb) * H_;
            for (int idx = tid; idx < 1024; idx += 384) {
                int b = idx >> 7, kk = (idx & 127) << 2;
                unsigned long long vh = __ldcg(
                    (const unsigned long long*)(hbh + base + (size_t)b * H_ + kk));
                unsigned long long vl = __ldcg(
                    (const unsigned long long*)(hbl + base + (size_t)b * H_ + kk));
                *(unsigned long long*)(smc + HH_OFF + (b * WROW + kk) * 2) = vh;
                *(unsigned long long*)(smc + HL_OFF + (b * WROW + kk) * 2) = vl;
            }
        }
        __syncthreads();

        // ---- tensor-core matvec: all 12 warps ----
        {
            float d0[4] = {0.f, 0.f, 0.f, 0.f};
            float d1[4] = {0.f, 0.f, 0.f, 0.f};
#pragma unroll
            for (int ps = 0; ps < 8; ++ps) {
                const unsigned pb = ps * 64;
                unsigned bh[4], bl[4], al0[4], al1[4];
                ldsm_x4(bh[0], bh[1], bh[2], bh[3], aBhi + pb);
                ldsm_x4(bl[0], bl[1], bl[2], bl[3], aBlo + pb);
                ldsm_x4(al0[0], al0[1], al0[2], al0[3], aAlo + (2 * ps) * 32);
                ldsm_x4(al1[0], al1[1], al1[2], al1[3], aAlo + (2 * ps + 1) * 32);
                const unsigned* a0 = aH[2 * ps];
                const unsigned* a1 = aH[2 * ps + 1];
                mma_bf16(d0[0], d0[1], d0[2], d0[3],
                         a0[0], a0[1], a0[2], a0[3], bh[0], bh[1]);
                mma_bf16(d0[0], d0[1], d0[2], d0[3],
                         a0[0], a0[1], a0[2], a0[3], bl[0], bl[1]);
                mma_bf16(d0[0], d0[1], d0[2], d0[3],
                         al0[0], al0[1], al0[2], al0[3], bh[0], bh[1]);
                mma_bf16(d1[0], d1[1], d1[2], d1[3],
                         a1[0], a1[1], a1[2], a1[3], bh[2], bh[3]);
                mma_bf16(d1[0], d1[1], d1[2], d1[3],
                         a1[0], a1[1], a1[2], a1[3], bl[2], bl[3]);
                mma_bf16(d1[0], d1[1], d1[2], d1[3],
                         al1[0], al1[1], al1[2], al1[3], bh[2], bh[3]);
            }
            float* rk = red + kh * 96 * 9;
            rk[(mt * 16 + fg)     * 9 + 2 * ft    ] = d0[0] + d1[0];
            rk[(mt * 16 + fg)     * 9 + 2 * ft + 1] = d0[1] + d1[1];
            rk[(mt * 16 + fg + 8) * 9 + 2 * ft    ] = d0[2] + d1[2];
            rk[(mt * 16 + fg + 8) * 9 + 2 * ft + 1] = d0[3] + d1[3];
        }
        __syncthreads();

        // ---- elementwise (threads 0-255) + early release ----
        if (tid < 256) {
            float ghr = red[(ei) * 9 + eb]      + red[96 * 9 + (ei) * 9 + eb];
            float ghz = red[(32 + ei) * 9 + eb] + red[96 * 9 + (32 + ei) * 9 + eb];
            float ghn = red[(64 + ei) * 9 + eb] + red[96 * 9 + (64 + ei) * 9 + eb];
            ghr += sb[ei];
            ghz += sb[32 + ei];
            ghn += sb[64 + ei];

            float r = sigmoidf_(xr + ghr);
            float z = sigmoidf_(xz + ghz);
            float n = tanhf_(xn + r * ghn);
            float hnew = n + z * (h_prev_reg - n);
            h_prev_reg = hnew;

            const size_t off = ((size_t)t * B_ + rb + eb) * H_ + ibase + ei;
            unsigned hb = bf16_bits(hnew);
            float rem = hnew - bf16_val(hb);
            hbh[off] = (unsigned short)hb;
            hbl[off] = (unsigned short)bf16_bits(rem);
            if (layer) __stcg(g_h2 + off, hnew);

            asm volatile("bar.sync 1, 256;" ::: "memory");
            if (tid == 0) red_release(ctr, 1u);
        }
        // MMA-only warps (8-11) proceed to next-step staging; they self-block
        // on the poll (own release above is part of the 16-count target).
    }
}

// ---------------------------------------------------------------------------
// Pool over batch + FC
// ---------------------------------------------------------------------------
__global__ __launch_bounds__(256) void pool_fc_kernel(
    const float* __restrict__ fcW, const float* __restrict__ fcb,
    float* __restrict__ out)
{
    __shared__ float rbuf[5][256];
    const int t = blockIdx.x;
    const int tid = threadIdx.x;

    float s0 = 0.f, s1 = 0.f;
    const float* base = g_h2 + (size_t)t * B_ * H_ + tid * 2;
#pragma unroll 8
    for (int b = 0; b < B_; ++b) {
        float2 vv = *(const float2*)(base + (size_t)b * H_);
        s0 += vv.x; s1 += vv.y;
    }
    s0 *= (1.0f / 64.0f);
    s1 *= (1.0f / 64.0f);

#pragma unroll
    for (int l = 0; l < L_; ++l)
        rbuf[l][tid] = s0 * __ldg(fcW + l * H_ + tid * 2)
                     + s1 * __ldg(fcW + l * H_ + tid * 2 + 1);
    __syncthreads();

    for (int s = 128; s > 0; s >>= 1) {
        if (tid < s) {
#pragma unroll
            for (int l = 0; l < L_; ++l) rbuf[l][tid] += rbuf[l][tid + s];
        }
        __syncthreads();
    }
    if (tid < L_) out[t * L_ + tid] = rbuf[tid][0] + __ldg(fcb + tid);
}

// ---------------------------------------------------------------------------
// launcher
// ---------------------------------------------------------------------------
extern "C" void kernel_launch(void* const* d_in, const int* in_sizes, int n_in,
                              void* d_out, int out_size) {
    (void)in_sizes; (void)n_in; (void)out_size;
    const int*   texts = (const int*)  d_in[0];
    const float* emb   = (const float*)d_in[1];
    const float* Wih0  = (const float*)d_in[2];
    const float* Whh0  = (const float*)d_in[3];
    const float* bih0  = (const float*)d_in[4];
    const float* bhh0  = (const float*)d_in[5];
    const float* Wih1  = (const float*)d_in[6];
    const float* Whh1  = (const float*)d_in[7];
    const float* bih1  = (const float*)d_in[8];
    const float* bhh1  = (const float*)d_in[9];
    const float* fcW   = (const float*)d_in[10];
    const float* fcb   = (const float*)d_in[11];
    float* out = (float*)d_out;

    cudaFuncSetAttribute(rec_kernel,
                         cudaFuncAttributeMaxDynamicSharedMemorySize,
                         SMEM_REC_BYTES);
    cudaFuncSetAttribute(proj_mma<EP_, 0>,
                         cudaFuncAttributeMaxDynamicSharedMemorySize, SMEM_PROJ);
    cudaFuncSetAttribute(proj_mma<H_, 1>,
                         cudaFuncAttributeMaxDynamicSharedMemorySize, SMEM_PROJ);

    init_ctr_kernel<<<1, 512>>>();
    cvt_all_kernel<<<4096, 256>>>(emb, Wih0, Wih1);
    noop_kernel<<<1, 32>>>();           // ncu ordinal #4 -> proj_mma<EP_,0>
    proj_mma<EP_, 0><<<dim3(12, 256), 256, SMEM_PROJ>>>(texts, bih0);
    rec_kernel<<<128, 384, SMEM_REC_BYTES>>>(Whh0, bhh0, 0);
    proj_mma<H_, 1><<<dim3(12, 256), 256, SMEM_PROJ>>>(nullptr, bih1);
    rec_kernel<<<128, 384, SMEM_REC_BYTES>>>(Whh1, bhh1, 1);
    pool_fc_kernel<<<512, 256>>>(fcW, fcb, out);
}

// round 16
// speedup vs baseline: 1.4349x; 1.0209x over previous
#include <cuda_runtime.h>
#include <cuda_bf16.h>
#include <math.h>
#include <stdint.h>

// Problem dims
#define T_  512
#define B_  64
#define E_  300
#define H_  512
#define L_  5
#define G3H 1536
#define M_  (T_*B_)          // 32768
#define V_  30000
#define EP_ 304              // E padded to k16 multiple

// ---------------------------------------------------------------------------
// Scratch (device globals — no runtime allocation allowed)
// ---------------------------------------------------------------------------
__device__ float g_xp0[(size_t)M_ * G3H];
__device__ float g_xp1[(size_t)M_ * G3H];
__device__ float g_h2 [(size_t)M_ * H_];
__device__ unsigned g_ctr2[2048];
// bf16 hi/lo split operands
__device__ unsigned short g_embh[(size_t)V_ * EP_];
__device__ unsigned short g_embl[(size_t)V_ * EP_];
__device__ unsigned short g_w0h[(size_t)G3H * EP_];
__device__ unsigned short g_w0l[(size_t)G3H * EP_];
__device__ unsigned short g_w1h[(size_t)G3H * H_];
__device__ unsigned short g_w1l[(size_t)G3H * H_];
__device__ unsigned short g_hbh[2 * (size_t)M_ * H_];
__device__ unsigned short g_hbl[2 * (size_t)M_ * H_];

// ---------------------------------------------------------------------------
// helpers
// ---------------------------------------------------------------------------
__device__ __forceinline__ unsigned ld_acquire(const unsigned* p) {
    unsigned v;
    asm volatile("ld.acquire.gpu.u32 %0, [%1];" : "=r"(v) : "l"(p) : "memory");
    return v;
}
__device__ __forceinline__ void red_release(unsigned* p, unsigned v) {
    asm volatile("red.release.gpu.global.add.u32 [%0], %1;" :: "l"(p), "r"(v) : "memory");
}
__device__ __forceinline__ float sigmoidf_(float x) {
    return 1.0f / (1.0f + __expf(-x));
}
__device__ __forceinline__ float tanhf_(float x) {
    return 1.0f - 2.0f / (__expf(2.0f * x) + 1.0f);
}
__device__ __forceinline__ unsigned smem_u32(const void* p) {
    unsigned a;
    asm("{ .reg .u64 t; cvta.to.shared.u64 t, %1; cvt.u32.u64 %0, t; }"
        : "=r"(a) : "l"(p));
    return a;
}
__device__ __forceinline__ unsigned bf16_bits(float x) {
    __nv_bfloat16 h = __float2bfloat16_rn(x);
    return (unsigned)(reinterpret_cast<__nv_bfloat16_raw&>(h).x);
}
__device__ __forceinline__ float bf16_val(unsigned bits) {
    __nv_bfloat16_raw r; r.x = (unsigned short)bits;
    return __bfloat162float(reinterpret_cast<__nv_bfloat16&>(r));
}
__device__ __forceinline__ void ldsm_x4(unsigned& r0, unsigned& r1,
                                        unsigned& r2, unsigned& r3, unsigned a) {
    asm volatile("ldmatrix.sync.aligned.m8n8.x4.shared.b16 {%0,%1,%2,%3},[%4];"
                 : "=r"(r0), "=r"(r1), "=r"(r2), "=r"(r3) : "r"(a));
}
__device__ __forceinline__ void mma_bf16(float& d0, float& d1, float& d2, float& d3,
                                         unsigned a0, unsigned a1, unsigned a2, unsigned a3,
                                         unsigned b0, unsigned b1) {
    asm volatile("mma.sync.aligned.m16n8k16.row.col.f32.bf16.bf16.f32 "
                 "{%0,%1,%2,%3},{%4,%5,%6,%7},{%8,%9},{%0,%1,%2,%3};"
                 : "+f"(d0), "+f"(d1), "+f"(d2), "+f"(d3)
                 : "r"(a0), "r"(a1), "r"(a2), "r"(a3), "r"(b0), "r"(b1));
}

__global__ void init_ctr_kernel() {
#pragma unroll
    for (int i = 0; i < 4; ++i)
        g_ctr2[threadIdx.x + i * 512] = 0u;
}

// ---------------------------------------------------------------------------
// Merged fp32 -> bf16 hi/lo split (emb + Wih0 + Wih1 in one launch).
// ---------------------------------------------------------------------------
__global__ void cvt_all_kernel(const float* __restrict__ emb,
                               const float* __restrict__ w0,
                               const float* __restrict__ w1) {
    const size_t N0 = (size_t)V_ * EP_;
    const size_t N1 = N0 + (size_t)G3H * EP_;
    const size_t N2 = N1 + (size_t)G3H * H_;
    for (size_t i = (size_t)blockIdx.x * blockDim.x + threadIdx.x; i < N2;
         i += (size_t)gridDim.x * blockDim.x) {
        const float* src; int ks, kd; size_t idx;
        unsigned short *dh, *dl;
        if (i < N0)      { src = emb; ks = E_; kd = EP_; idx = i;      dh = g_embh; dl = g_embl; }
        else if (i < N1) { src = w0;  ks = E_; kd = EP_; idx = i - N0; dh = g_w0h;  dl = g_w0l; }
        else             { src = w1;  ks = H_; kd = H_;  idx = i - N1; dh = g_w1h;  dl = g_w1l; }
        int r = (int)(idx / kd);
        int c = (int)(idx - (size_t)r * kd);
        float v = (c < ks) ? src[(size_t)r * ks + c] : 0.f;
        unsigned h = bf16_bits(v);
        dh[idx] = (unsigned short)h;
        dl[idx] = (unsigned short)bf16_bits(v - bf16_val(h));
    }
}

// ---------------------------------------------------------------------------
// Tensor-core projection GEMM (mma.sync, 2 CTAs/SM — proven R15)
// ---------------------------------------------------------------------------
#define PROW 24
#define PMAT 6144
#define PSTG 24576
#define SMEM_PROJ (2 * PSTG)

template <int K, int SRC>
__global__ __launch_bounds__(256, 2) void proj_mma(
    const int* __restrict__ gidx, const float* __restrict__ bias)
{
    extern __shared__ __align__(16) char smp[];
    const unsigned short* Ah = (SRC == 0) ? g_embh : g_hbh;
    const unsigned short* Al = (SRC == 0) ? g_embl : g_hbl;
    const unsigned short* Wh = (SRC == 0) ? g_w0h : g_w1h;
    const unsigned short* Wl = (SRC == 0) ? g_w0l : g_w1l;
    float* C = (SRC == 0) ? g_xp0 : g_xp1;

    const int tid = threadIdx.x;
    const int li  = tid & 31;
    const int w   = tid >> 5;
    const int wm  = w >> 1;
    const int wn  = w & 1;
    const int m0  = blockIdx.y * 128;
    const int n0  = blockIdx.x * 128;
    const unsigned sbase = smem_u32(smp);

    const int lrow  = tid >> 1;
    const int lhalf = tid & 1;
    size_t arow;
    if (SRC == 0) arow = (size_t)__ldg(gidx + m0 + lrow) * K;
    else          arow = (size_t)(m0 + lrow) * K;
    const size_t brow = (size_t)(n0 + lrow) * K;
    const unsigned sst = (unsigned)(lrow * PROW + lhalf * 8) * 2;

    float acc[2][8][4];
#pragma unroll
    for (int a = 0; a < 2; ++a)
#pragma unroll
        for (int b = 0; b < 8; ++b)
#pragma unroll
            for (int c = 0; c < 4; ++c) acc[a][b][c] = 0.f;

    const int KT = K / 16;
    uint4 rAh, rAl, rBh, rBl;
    {
        const int k0 = lhalf * 8;
        rAh = *(const uint4*)(Ah + arow + k0);
        rAl = *(const uint4*)(Al + arow + k0);
        rBh = *(const uint4*)(Wh + brow + k0);
        rBl = *(const uint4*)(Wl + brow + k0);
        *(uint4*)(smp + 0 * PMAT + sst) = rAh;
        *(uint4*)(smp + 1 * PMAT + sst) = rAl;
        *(uint4*)(smp + 2 * PMAT + sst) = rBh;
        *(uint4*)(smp + 3 * PMAT + sst) = rBl;
    }
    __syncthreads();

    const unsigned aoff = (unsigned)((wm * 32 + (li & 15)) * PROW + (li >> 4) * 8) * 2;
    const unsigned boff = (unsigned)((wn * 64 + (li & 15)) * PROW + (li >> 4) * 8) * 2;

    for (int kt = 0; kt < KT; ++kt) {
        const unsigned sb0 = sbase + (unsigned)(kt & 1) * PSTG;
        if (kt + 1 < KT) {
            const int k0 = (kt + 1) * 16 + lhalf * 8;
            rAh = *(const uint4*)(Ah + arow + k0);
            rAl = *(const uint4*)(Al + arow + k0);
            rBh = *(const uint4*)(Wh + brow + k0);
            rBl = *(const uint4*)(Wl + brow + k0);
        }

        unsigned aH[2][4], aL[2][4];
#pragma unroll
        for (int mt = 0; mt < 2; ++mt) {
            ldsm_x4(aH[mt][0], aH[mt][1], aH[mt][2], aH[mt][3],
                    sb0 + 0 * PMAT + aoff + mt * 768);
            ldsm_x4(aL[mt][0], aL[mt][1], aL[mt][2], aL[mt][3],
                    sb0 + 1 * PMAT + aoff + mt * 768);
        }
#pragma unroll
        for (int ng = 0; ng < 4; ++ng) {
            unsigned bh[4], bl[4];
            ldsm_x4(bh[0], bh[1], bh[2], bh[3], sb0 + 2 * PMAT + boff + ng * 768);
            ldsm_x4(bl[0], bl[1], bl[2], bl[3], sb0 + 3 * PMAT + boff + ng * 768);
#pragma unroll
            for (int mt = 0; mt < 2; ++mt) {
                float* d0 = acc[mt][2 * ng];
                mma_bf16(d0[0], d0[1], d0[2], d0[3],
                         aH[mt][0], aH[mt][1], aH[mt][2], aH[mt][3], bh[0], bh[2]);
                mma_bf16(d0[0], d0[1], d0[2], d0[3],
                         aH[mt][0], aH[mt][1], aH[mt][2], aH[mt][3], bl[0], bl[2]);
                mma_bf16(d0[0], d0[1], d0[2], d0[3],
                         aL[mt][0], aL[mt][1], aL[mt][2], aL[mt][3], bh[0], bh[2]);
                float* d1 = acc[mt][2 * ng + 1];
                mma_bf16(d1[0], d1[1], d1[2], d1[3],
                         aH[mt][0], aH[mt][1], aH[mt][2], aH[mt][3], bh[1], bh[3]);
                mma_bf16(d1[0], d1[1], d1[2], d1[3],
                         aH[mt][0], aH[mt][1], aH[mt][2], aH[mt][3], bl[1], bl[3]);
                mma_bf16(d1[0], d1[1], d1[2], d1[3],
                         aL[mt][0], aL[mt][1], aL[mt][2], aL[mt][3], bh[1], bh[3]);
            }
        }
        if (kt + 1 < KT) {
            char* nb = smp + ((kt & 1) ^ 1) * PSTG;
            *(uint4*)(nb + 0 * PMAT + sst) = rAh;
            *(uint4*)(nb + 1 * PMAT + sst) = rAl;
            *(uint4*)(nb + 2 * PMAT + sst) = rBh;
            *(uint4*)(nb + 3 * PMAT + sst) = rBl;
            __syncthreads();
        }
    }

    const int fg = li >> 2;
    const int ft = li & 3;
#pragma unroll
    for (int mt = 0; mt < 2; ++mt) {
#pragma unroll
        for (int nt = 0; nt < 8; ++nt) {
            const int row = m0 + wm * 32 + mt * 16 + fg;
            const int col = n0 + wn * 64 + nt * 8 + 2 * ft;
            const float b0 = __ldg(bias + col);
            const float b1 = __ldg(bias + col + 1);
            float* c0 = C + (size_t)row * G3H + col;
            float* c1 = C + (size_t)(row + 8) * G3H + col;
            *(float2*)c0 = make_float2(acc[mt][nt][0] + b0, acc[mt][nt][1] + b1);
            *(float2*)c1 = make_float2(acc[mt][nt][2] + b0, acc[mt][nt][3] + b1);
        }
    }
}

// ---------------------------------------------------------------------------
// Persistent GRU recurrence — R11 core + poll backoff + xp prefetch rotate.
// ---------------------------------------------------------------------------
#define WROW    520
#define WH_OFF  0
#define WL_OFF  99840
#define HH_OFF  199680
#define HL_OFF  208000
#define RED_OFF 216320
#define SB_OFF  223232
#define SMEM_REC_BYTES 223616

__global__ __launch_bounds__(384, 1) void rec_kernel(
    const float* __restrict__ Whh, const float* __restrict__ bhh, int layer)
{
    extern __shared__ char smc[];
    float* red = (float*)(smc + RED_OFF);
    float* sb  = (float*)(smc + SB_OFF);
    const unsigned sbase = smem_u32(smc);

    const float* xp = layer ? g_xp1 : g_xp0;

    const int tid   = threadIdx.x;
    const int wid   = tid >> 5;
    const int li    = tid & 31;
    const int bid   = blockIdx.x;
    const int group = bid >> 4;
    const int gidx  = bid & 15;
    const int rb    = group * 8;
    const int ibase = gidx * 32;
    unsigned* ctr = g_ctr2 + (layer * 8 + group) * 32;

    unsigned short* hbh = g_hbh + (size_t)layer * M_ * H_;
    unsigned short* hbl = g_hbl + (size_t)layer * M_ * H_;

    // ---- preload weights (bf16 hi/lo split) + bias ----
    for (int idx = tid; idx < 96 * 256; idx += 384) {
        int r  = idx >> 8;
        int kk = (idx & 255) << 1;
        int gr = (r >> 5) * 512 + ibase + (r & 31);
        float2 wv = *(const float2*)(Whh + (size_t)gr * 512 + kk);
        unsigned h0 = bf16_bits(wv.x), h1 = bf16_bits(wv.y);
        unsigned l0 = bf16_bits(wv.x - bf16_val(h0));
        unsigned l1 = bf16_bits(wv.y - bf16_val(h1));
        *(unsigned*)(smc + WH_OFF + (r * WROW + kk) * 2) = (h1 << 16) | h0;
        *(unsigned*)(smc + WL_OFF + (r * WROW + kk) * 2) = (l1 << 16) | l0;
    }
    if (tid < 96) {
        int gr = (tid >> 5) * 512 + ibase + (tid & 31);
        sb[tid] = __ldg(bhh + gr);
    }
    __syncthreads();

    // MMA warp roles
    const int mt = wid % 6;
    const int kh = wid / 6;
    const int k0 = kh * 256;
    const int la = li & 15;
    const unsigned aoff = ((mt * 16 + la) * WROW + k0 + ((li >> 4) & 1) * 8) * 2;
    const unsigned aAhi = sbase + WH_OFF + aoff;
    const unsigned aAlo = sbase + WL_OFF + aoff;
    const unsigned boff4 = (((li & 7) * WROW) + k0 + ((li >> 3) & 3) * 8) * 2;
    const unsigned aBhi = sbase + HH_OFF + boff4;
    const unsigned aBlo = sbase + HL_OFF + boff4;
    const int fg = li >> 2;
    const int ft = li & 3;
    const int eb = tid >> 5;
    const int ei = tid & 31;

    // ---- A-hi fragments: register-resident for the whole kernel ----
    unsigned aH[16][4];
#pragma unroll
    for (int ks = 0; ks < 16; ++ks)
        ldsm_x4(aH[ks][0], aH[ks][1], aH[ks][2], aH[ks][3], aAhi + ks * 32);

    float h_prev_reg = 0.f;

    // ---- xp prefetch for t=0 ----
    float xr = 0.f, xz = 0.f, xn = 0.f;
    if (tid < 256) {
        const float* xrow = xp + ((size_t)rb + eb) * G3H + ibase + ei;
        xr = __ldg(xrow);
        xz = __ldg(xrow + 512);
        xn = __ldg(xrow + 1024);
    }

    for (int t = 0; t < T_; ++t) {
        // ---- per-warp poll (nanosleep backoff) + u64 staging ----
        if (t == 0) {
            for (int idx = tid; idx < 2048; idx += 384) {
                int b = idx >> 8, kk = (idx & 255) << 1;
                *(unsigned*)(smc + HH_OFF + (b * WROW + kk) * 2) = 0u;
                *(unsigned*)(smc + HL_OFF + (b * WROW + kk) * 2) = 0u;
            }
        } else {
            if (li == 0) {
                unsigned target = 16u * (unsigned)t;
                if (ld_acquire(ctr) < target) {
                    while (ld_acquire(ctr) < target) __nanosleep(32);
                }
            }
            __syncwarp();
            const size_t base = ((size_t)(t - 1) * B_ + rb) * H_;
            for (int idx = tid; idx < 1024; idx += 384) {
                int b = idx >> 7, kk = (idx & 127) << 2;
                unsigned long long vh = __ldcg(
                    (const unsigned long long*)(hbh + base + (size_t)b * H_ + kk));
                unsigned long long vl = __ldcg(
                    (const unsigned long long*)(hbl + base + (size_t)b * H_ + kk));
                *(unsigned long long*)(smc + HH_OFF + (b * WROW + kk) * 2) = vh;
                *(unsigned long long*)(smc + HL_OFF + (b * WROW + kk) * 2) = vl;
            }
        }
        __syncthreads();

        // ---- tensor-core matvec: all 12 warps ----
        {
            float d0[4] = {0.f, 0.f, 0.f, 0.f};
            float d1[4] = {0.f, 0.f, 0.f, 0.f};
#pragma unroll
            for (int ps = 0; ps < 8; ++ps) {
                const unsigned pb = ps * 64;
                unsigned bh[4], bl[4], al0[4], al1[4];
                ldsm_x4(bh[0], bh[1], bh[2], bh[3], aBhi + pb);
                ldsm_x4(bl[0], bl[1], bl[2], bl[3], aBlo + pb);
                ldsm_x4(al0[0], al0[1], al0[2], al0[3], aAlo + (2 * ps) * 32);
                ldsm_x4(al1[0], al1[1], al1[2], al1[3], aAlo + (2 * ps + 1) * 32);
                const unsigned* a0 = aH[2 * ps];
                const unsigned* a1 = aH[2 * ps + 1];
                mma_bf16(d0[0], d0[1], d0[2], d0[3],
                         a0[0], a0[1], a0[2], a0[3], bh[0], bh[1]);
                mma_bf16(d0[0], d0[1], d0[2], d0[3],
                         a0[0], a0[1], a0[2], a0[3], bl[0], bl[1]);
                mma_bf16(d0[0], d0[1], d0[2], d0[3],
                         al0[0], al0[1], al0[2], al0[3], bh[0], bh[1]);
                mma_bf16(d1[0], d1[1], d1[2], d1[3],
                         a1[0], a1[1], a1[2], a1[3], bh[2], bh[3]);
                mma_bf16(d1[0], d1[1], d1[2], d1[3],
                         a1[0], a1[1], a1[2], a1[3], bl[2], bl[3]);
                mma_bf16(d1[0], d1[1], d1[2], d1[3],
                         al1[0], al1[1], al1[2], al1[3], bh[2], bh[3]);
            }
            float* rk = red + kh * 96 * 9;
            rk[(mt * 16 + fg)     * 9 + 2 * ft    ] = d0[0] + d1[0];
            rk[(mt * 16 + fg)     * 9 + 2 * ft + 1] = d0[1] + d1[1];
            rk[(mt * 16 + fg + 8) * 9 + 2 * ft    ] = d0[2] + d1[2];
            rk[(mt * 16 + fg + 8) * 9 + 2 * ft + 1] = d0[3] + d1[3];
        }
        __syncthreads();

        // ---- elementwise (threads 0-255) + early release + xp(t+1) load ----
        if (tid < 256) {
            float ghr = red[(ei) * 9 + eb]      + red[96 * 9 + (ei) * 9 + eb];
            float ghz = red[(32 + ei) * 9 + eb] + red[96 * 9 + (32 + ei) * 9 + eb];
            float ghn = red[(64 + ei) * 9 + eb] + red[96 * 9 + (64 + ei) * 9 + eb];
            ghr += sb[ei];
            ghz += sb[32 + ei];
            ghn += sb[64 + ei];

            float r = sigmoidf_(xr + ghr);
            float z = sigmoidf_(xz + ghz);
            float n = tanhf_(xn + r * ghn);
            float hnew = n + z * (h_prev_reg - n);
            h_prev_reg = hnew;

            const size_t off = ((size_t)t * B_ + rb + eb) * H_ + ibase + ei;
            unsigned hb = bf16_bits(hnew);
            float rem = hnew - bf16_val(hb);
            hbh[off] = (unsigned short)hb;
            hbl[off] = (unsigned short)bf16_bits(rem);
            if (layer) __stcg(g_h2 + off, hnew);

            asm volatile("bar.sync 1, 256;" ::: "memory");
            if (tid == 0) red_release(ctr, 1u);

            // prefetch xp for step t+1 (full next-step exchange as slack)
            if (t + 1 < T_) {
                const float* xrow = xp + ((size_t)(t + 1) * B_ + rb + eb) * G3H
                                  + ibase + ei;
                xr = __ldg(xrow);
                xz = __ldg(xrow + 512);
                xn = __ldg(xrow + 1024);
            }
        }
        // MMA-only warps (8-11) proceed to next-step staging; they self-block
        // on the poll (own release above is part of the 16-count target).
    }
}

// ---------------------------------------------------------------------------
// Pool over batch + FC
// ---------------------------------------------------------------------------
__global__ __launch_bounds__(256) void pool_fc_kernel(
    const float* __restrict__ fcW, const float* __restrict__ fcb,
    float* __restrict__ out)
{
    __shared__ float rbuf[5][256];
    const int t = blockIdx.x;
    const int tid = threadIdx.x;

    float s0 = 0.f, s1 = 0.f;
    const float* base = g_h2 + (size_t)t * B_ * H_ + tid * 2;
#pragma unroll 8
    for (int b = 0; b < B_; ++b) {
        float2 vv = *(const float2*)(base + (size_t)b * H_);
        s0 += vv.x; s1 += vv.y;
    }
    s0 *= (1.0f / 64.0f);
    s1 *= (1.0f / 64.0f);

#pragma unroll
    for (int l = 0; l < L_; ++l)
        rbuf[l][tid] = s0 * __ldg(fcW + l * H_ + tid * 2)
                     + s1 * __ldg(fcW + l * H_ + tid * 2 + 1);
    __syncthreads();

    for (int s = 128; s > 0; s >>= 1) {
        if (tid < s) {
#pragma unroll
            for (int l = 0; l < L_; ++l) rbuf[l][tid] += rbuf[l][tid + s];
        }
        __syncthreads();
    }
    if (tid < L_) out[t * L_ + tid] = rbuf[tid][0] + __ldg(fcb + tid);
}

// ---------------------------------------------------------------------------
// launcher
// ---------------------------------------------------------------------------
extern "C" void kernel_launch(void* const* d_in, const int* in_sizes, int n_in,
                              void* d_out, int out_size) {
    (void)in_sizes; (void)n_in; (void)out_size;
    const int*   texts = (const int*)  d_in[0];
    const float* emb   = (const float*)d_in[1];
    const float* Wih0  = (const float*)d_in[2];
    const float* Whh0  = (const float*)d_in[3];
    const float* bih0  = (const float*)d_in[4];
    const float* bhh0  = (const float*)d_in[5];
    const float* Wih1  = (const float*)d_in[6];
    const float* Whh1  = (const float*)d_in[7];
    const float* bih1  = (const float*)d_in[8];
    const float* bhh1  = (const float*)d_in[9];
    const float* fcW   = (const float*)d_in[10];
    const float* fcb   = (const float*)d_in[11];
    float* out = (float*)d_out;

    cudaFuncSetAttribute(rec_kernel,
                         cudaFuncAttributeMaxDynamicSharedMemorySize,
                         SMEM_REC_BYTES);
    cudaFuncSetAttribute(proj_mma<EP_, 0>,
                         cudaFuncAttributeMaxDynamicSharedMemorySize, SMEM_PROJ);
    cudaFuncSetAttribute(proj_mma<H_, 1>,
                         cudaFuncAttributeMaxDynamicSharedMemorySize, SMEM_PROJ);

    init_ctr_kernel<<<1, 512>>>();
    cvt_all_kernel<<<4096, 256>>>(emb, Wih0, Wih1);
    proj_mma<EP_, 0><<<dim3(12, 256), 256, SMEM_PROJ>>>(texts, bih0);
    rec_kernel<<<128, 384, SMEM_REC_BYTES>>>(Whh0, bhh0, 0);
    proj_mma<H_, 1><<<dim3(12, 256), 256, SMEM_PROJ>>>(nullptr, bih1);
    rec_kernel<<<128, 384, SMEM_REC_BYTES>>>(Whh1, bhh1, 1);
    pool_fc_kernel<<<512, 256>>>(fcW, fcb, out);
}

// round 17
// speedup vs baseline: 1.5771x; 1.0991x over previous
#include <cuda_runtime.h>
#include <cuda_bf16.h>
#include <math.h>
#include <stdint.h>

// Problem dims
#define T_  512
#define B_  64
#define E_  300
#define H_  512
#define L_  5
#define G3H 1536
#define M_  (T_*B_)          // 32768
#define V_  30000
#define EP_ 304              // E padded to k16 multiple

// ---------------------------------------------------------------------------
// Scratch (device globals — no runtime allocation allowed)
// ---------------------------------------------------------------------------
__device__ float g_xp0[(size_t)M_ * G3H];
__device__ float g_xp1[(size_t)M_ * G3H];
__device__ float g_h2 [(size_t)M_ * H_];
__device__ unsigned g_ctr2[2048];
// bf16 hi/lo split operands
__device__ unsigned short g_embh[(size_t)V_ * EP_];
__device__ unsigned short g_embl[(size_t)V_ * EP_];
__device__ unsigned short g_w0h[(size_t)G3H * EP_];
__device__ unsigned short g_w0l[(size_t)G3H * EP_];
__device__ unsigned short g_w1h[(size_t)G3H * H_];
__device__ unsigned short g_w1l[(size_t)G3H * H_];
__device__ unsigned short g_hbh[2 * (size_t)M_ * H_];
__device__ unsigned short g_hbl[2 * (size_t)M_ * H_];

// ---------------------------------------------------------------------------
// helpers
// ---------------------------------------------------------------------------
__device__ __forceinline__ unsigned ld_acquire(const unsigned* p) {
    unsigned v;
    asm volatile("ld.acquire.gpu.u32 %0, [%1];" : "=r"(v) : "l"(p) : "memory");
    return v;
}
__device__ __forceinline__ void red_release(unsigned* p, unsigned v) {
    asm volatile("red.release.gpu.global.add.u32 [%0], %1;" :: "l"(p), "r"(v) : "memory");
}
__device__ __forceinline__ float sigmoidf_(float x) {
    return 1.0f / (1.0f + __expf(-x));
}
__device__ __forceinline__ float tanhf_(float x) {
    return 1.0f - 2.0f / (__expf(2.0f * x) + 1.0f);
}
__device__ __forceinline__ unsigned smem_u32(const void* p) {
    unsigned a;
    asm("{ .reg .u64 t; cvta.to.shared.u64 t, %1; cvt.u32.u64 %0, t; }"
        : "=r"(a) : "l"(p));
    return a;
}
__device__ __forceinline__ unsigned bf16_bits(float x) {
    __nv_bfloat16 h = __float2bfloat16_rn(x);
    return (unsigned)(reinterpret_cast<__nv_bfloat16_raw&>(h).x);
}
__device__ __forceinline__ float bf16_val(unsigned bits) {
    __nv_bfloat16_raw r; r.x = (unsigned short)bits;
    return __bfloat162float(reinterpret_cast<__nv_bfloat16&>(r));
}
__device__ __forceinline__ void ldsm_x4(unsigned& r0, unsigned& r1,
                                        unsigned& r2, unsigned& r3, unsigned a) {
    asm volatile("ldmatrix.sync.aligned.m8n8.x4.shared.b16 {%0,%1,%2,%3},[%4];"
                 : "=r"(r0), "=r"(r1), "=r"(r2), "=r"(r3) : "r"(a));
}
__device__ __forceinline__ void mma_bf16(float& d0, float& d1, float& d2, float& d3,
                                         unsigned a0, unsigned a1, unsigned a2, unsigned a3,
                                         unsigned b0, unsigned b1) {
    asm volatile("mma.sync.aligned.m16n8k16.row.col.f32.bf16.bf16.f32 "
                 "{%0,%1,%2,%3},{%4,%5,%6,%7},{%8,%9},{%0,%1,%2,%3};"
                 : "+f"(d0), "+f"(d1), "+f"(d2), "+f"(d3)
                 : "r"(a0), "r"(a1), "r"(a2), "r"(a3), "r"(b0), "r"(b1));
}

__global__ void init_ctr_kernel() {
#pragma unroll
    for (int i = 0; i < 4; ++i)
        g_ctr2[threadIdx.x + i * 512] = 0u;
}

// ---------------------------------------------------------------------------
// Merged fp32 -> bf16 hi/lo split (emb + Wih0 + Wih1 in one launch).
// ---------------------------------------------------------------------------
__global__ void cvt_all_kernel(const float* __restrict__ emb,
                               const float* __restrict__ w0,
                               const float* __restrict__ w1) {
    const size_t N0 = (size_t)V_ * EP_;
    const size_t N1 = N0 + (size_t)G3H * EP_;
    const size_t N2 = N1 + (size_t)G3H * H_;
    for (size_t i = (size_t)blockIdx.x * blockDim.x + threadIdx.x; i < N2;
         i += (size_t)gridDim.x * blockDim.x) {
        const float* src; int ks, kd; size_t idx;
        unsigned short *dh, *dl;
        if (i < N0)      { src = emb; ks = E_; kd = EP_; idx = i;      dh = g_embh; dl = g_embl; }
        else if (i < N1) { src = w0;  ks = E_; kd = EP_; idx = i - N0; dh = g_w0h;  dl = g_w0l; }
        else             { src = w1;  ks = H_; kd = H_;  idx = i - N1; dh = g_w1h;  dl = g_w1l; }
        int r = (int)(idx / kd);
        int c = (int)(idx - (size_t)r * kd);
        float v = (c < ks) ? src[(size_t)r * ks + c] : 0.f;
        unsigned h = bf16_bits(v);
        dh[idx] = (unsigned short)h;
        dl[idx] = (unsigned short)bf16_bits(v - bf16_val(h));
    }
}

// ---------------------------------------------------------------------------
// Tensor-core projection GEMM (mma.sync, 2 CTAs/SM).
// 2-PRODUCT split: activations (A) plain bf16 hi; weights (B) hi/lo
// compensated. Removes the A-lo plane: 1/3 fewer HMMA, 4 fewer LDSM/kt,
// smem stage 48KB -> 36KB.
// ---------------------------------------------------------------------------
#define PROW 24
#define PMAT 6144
#define PSTG 18432                       // 3 matrices per stage (Ah, Bh, Bl)
#define SMEM_PROJ (2 * PSTG)             // 36864 B

template <int K, int SRC>
__global__ __launch_bounds__(256, 2) void proj_mma(
    const int* __restrict__ gidx, const float* __restrict__ bias)
{
    extern __shared__ __align__(16) char smp[];
    const unsigned short* Ah = (SRC == 0) ? g_embh : g_hbh;
    const unsigned short* Wh = (SRC == 0) ? g_w0h : g_w1h;
    const unsigned short* Wl = (SRC == 0) ? g_w0l : g_w1l;
    float* C = (SRC == 0) ? g_xp0 : g_xp1;

    const int tid = threadIdx.x;
    const int li  = tid & 31;
    const int w   = tid >> 5;
    const int wm  = w >> 1;
    const int wn  = w & 1;
    const int m0  = blockIdx.y * 128;
    const int n0  = blockIdx.x * 128;
    const unsigned sbase = smem_u32(smp);

    const int lrow  = tid >> 1;
    const int lhalf = tid & 1;
    size_t arow;
    if (SRC == 0) arow = (size_t)__ldg(gidx + m0 + lrow) * K;
    else          arow = (size_t)(m0 + lrow) * K;
    const size_t brow = (size_t)(n0 + lrow) * K;
    const unsigned sst = (unsigned)(lrow * PROW + lhalf * 8) * 2;

    float acc[2][8][4];
#pragma unroll
    for (int a = 0; a < 2; ++a)
#pragma unroll
        for (int b = 0; b < 8; ++b)
#pragma unroll
            for (int c = 0; c < 4; ++c) acc[a][b][c] = 0.f;

    const int KT = K / 16;
    uint4 rAh, rBh, rBl;
    {
        const int k0 = lhalf * 8;
        rAh = *(const uint4*)(Ah + arow + k0);
        rBh = *(const uint4*)(Wh + brow + k0);
        rBl = *(const uint4*)(Wl + brow + k0);
        *(uint4*)(smp + 0 * PMAT + sst) = rAh;
        *(uint4*)(smp + 1 * PMAT + sst) = rBh;
        *(uint4*)(smp + 2 * PMAT + sst) = rBl;
    }
    __syncthreads();

    const unsigned aoff = (unsigned)((wm * 32 + (li & 15)) * PROW + (li >> 4) * 8) * 2;
    const unsigned boff = (unsigned)((wn * 64 + (li & 15)) * PROW + (li >> 4) * 8) * 2;

    for (int kt = 0; kt < KT; ++kt) {
        const unsigned sb0 = sbase + (unsigned)(kt & 1) * PSTG;
        if (kt + 1 < KT) {
            const int k0 = (kt + 1) * 16 + lhalf * 8;
            rAh = *(const uint4*)(Ah + arow + k0);
            rBh = *(const uint4*)(Wh + brow + k0);
            rBl = *(const uint4*)(Wl + brow + k0);
        }

        unsigned aH[2][4];
#pragma unroll
        for (int mt = 0; mt < 2; ++mt)
            ldsm_x4(aH[mt][0], aH[mt][1], aH[mt][2], aH[mt][3],
                    sb0 + 0 * PMAT + aoff + mt * 768);
#pragma unroll
        for (int ng = 0; ng < 4; ++ng) {
            unsigned bh[4], bl[4];
            ldsm_x4(bh[0], bh[1], bh[2], bh[3], sb0 + 1 * PMAT + boff + ng * 768);
            ldsm_x4(bl[0], bl[1], bl[2], bl[3], sb0 + 2 * PMAT + boff + ng * 768);
#pragma unroll
            for (int mt = 0; mt < 2; ++mt) {
                float* d0 = acc[mt][2 * ng];
                mma_bf16(d0[0], d0[1], d0[2], d0[3],
                         aH[mt][0], aH[mt][1], aH[mt][2], aH[mt][3], bh[0], bh[2]);
                mma_bf16(d0[0], d0[1], d0[2], d0[3],
                         aH[mt][0], aH[mt][1], aH[mt][2], aH[mt][3], bl[0], bl[2]);
                float* d1 = acc[mt][2 * ng + 1];
                mma_bf16(d1[0], d1[1], d1[2], d1[3],
                         aH[mt][0], aH[mt][1], aH[mt][2], aH[mt][3], bh[1], bh[3]);
                mma_bf16(d1[0], d1[1], d1[2], d1[3],
                         aH[mt][0], aH[mt][1], aH[mt][2], aH[mt][3], bl[1], bl[3]);
            }
        }
        if (kt + 1 < KT) {
            char* nb = smp + ((kt & 1) ^ 1) * PSTG;
            *(uint4*)(nb + 0 * PMAT + sst) = rAh;
            *(uint4*)(nb + 1 * PMAT + sst) = rBh;
            *(uint4*)(nb + 2 * PMAT + sst) = rBl;
            __syncthreads();
        }
    }

    const int fg = li >> 2;
    const int ft = li & 3;
#pragma unroll
    for (int mt = 0; mt < 2; ++mt) {
#pragma unroll
        for (int nt = 0; nt < 8; ++nt) {
            const int row = m0 + wm * 32 + mt * 16 + fg;
            const int col = n0 + wn * 64 + nt * 8 + 2 * ft;
            const float b0 = __ldg(bias + col);
            const float b1 = __ldg(bias + col + 1);
            float* c0 = C + (size_t)row * G3H + col;
            float* c1 = C + (size_t)(row + 8) * G3H + col;
            *(float2*)c0 = make_float2(acc[mt][nt][0] + b0, acc[mt][nt][1] + b1);
            *(float2*)c1 = make_float2(acc[mt][nt][2] + b0, acc[mt][nt][3] + b1);
        }
    }
}

// ---------------------------------------------------------------------------
// Persistent GRU recurrence — R16 kernel VERBATIM (proven 4048 us).
// ---------------------------------------------------------------------------
#define WROW    520
#define WH_OFF  0
#define WL_OFF  99840
#define HH_OFF  199680
#define HL_OFF  208000
#define RED_OFF 216320
#define SB_OFF  223232
#define SMEM_REC_BYTES 223616

__global__ __launch_bounds__(384, 1) void rec_kernel(
    const float* __restrict__ Whh, const float* __restrict__ bhh, int layer)
{
    extern __shared__ char smc[];
    float* red = (float*)(smc + RED_OFF);
    float* sb  = (float*)(smc + SB_OFF);
    const unsigned sbase = smem_u32(smc);

    const float* xp = layer ? g_xp1 : g_xp0;

    const int tid   = threadIdx.x;
    const int wid   = tid >> 5;
    const int li    = tid & 31;
    const int bid   = blockIdx.x;
    const int group = bid >> 4;
    const int gidx  = bid & 15;
    const int rb    = group * 8;
    const int ibase = gidx * 32;
    unsigned* ctr = g_ctr2 + (layer * 8 + group) * 32;

    unsigned short* hbh = g_hbh + (size_t)layer * M_ * H_;
    unsigned short* hbl = g_hbl + (size_t)layer * M_ * H_;

    // ---- preload weights (bf16 hi/lo split) + bias ----
    for (int idx = tid; idx < 96 * 256; idx += 384) {
        int r  = idx >> 8;
        int kk = (idx & 255) << 1;
        int gr = (r >> 5) * 512 + ibase + (r & 31);
        float2 wv = *(const float2*)(Whh + (size_t)gr * 512 + kk);
        unsigned h0 = bf16_bits(wv.x), h1 = bf16_bits(wv.y);
        unsigned l0 = bf16_bits(wv.x - bf16_val(h0));
        unsigned l1 = bf16_bits(wv.y - bf16_val(h1));
        *(unsigned*)(smc + WH_OFF + (r * WROW + kk) * 2) = (h1 << 16) | h0;
        *(unsigned*)(smc + WL_OFF + (r * WROW + kk) * 2) = (l1 << 16) | l0;
    }
    if (tid < 96) {
        int gr = (tid >> 5) * 512 + ibase + (tid & 31);
        sb[tid] = __ldg(bhh + gr);
    }
    __syncthreads();

    // MMA warp roles
    const int mt = wid % 6;
    const int kh = wid / 6;
    const int k0 = kh * 256;
    const int la = li & 15;
    const unsigned aoff = ((mt * 16 + la) * WROW + k0 + ((li >> 4) & 1) * 8) * 2;
    const unsigned aAhi = sbase + WH_OFF + aoff;
    const unsigned aAlo = sbase + WL_OFF + aoff;
    const unsigned boff4 = (((li & 7) * WROW) + k0 + ((li >> 3) & 3) * 8) * 2;
    const unsigned aBhi = sbase + HH_OFF + boff4;
    const unsigned aBlo = sbase + HL_OFF + boff4;
    const int fg = li >> 2;
    const int ft = li & 3;
    const int eb = tid >> 5;
    const int ei = tid & 31;

    // ---- A-hi fragments: register-resident for the whole kernel ----
    unsigned aH[16][4];
#pragma unroll
    for (int ks = 0; ks < 16; ++ks)
        ldsm_x4(aH[ks][0], aH[ks][1], aH[ks][2], aH[ks][3], aAhi + ks * 32);

    float h_prev_reg = 0.f;

    // ---- xp prefetch for t=0 ----
    float xr = 0.f, xz = 0.f, xn = 0.f;
    if (tid < 256) {
        const float* xrow = xp + ((size_t)rb + eb) * G3H + ibase + ei;
        xr = __ldg(xrow);
        xz = __ldg(xrow + 512);
        xn = __ldg(xrow + 1024);
    }

    for (int t = 0; t < T_; ++t) {
        // ---- per-warp poll (nanosleep backoff) + u64 staging ----
        if (t == 0) {
            for (int idx = tid; idx < 2048; idx += 384) {
                int b = idx >> 8, kk = (idx & 255) << 1;
                *(unsigned*)(smc + HH_OFF + (b * WROW + kk) * 2) = 0u;
                *(unsigned*)(smc + HL_OFF + (b * WROW + kk) * 2) = 0u;
            }
        } else {
            if (li == 0) {
                unsigned target = 16u * (unsigned)t;
                if (ld_acquire(ctr) < target) {
                    while (ld_acquire(ctr) < target) __nanosleep(32);
                }
            }
            __syncwarp();
            const size_t base = ((size_t)(t - 1) * B_ + rb) * H_;
            for (int idx = tid; idx < 1024; idx += 384) {
                int b = idx >> 7, kk = (idx & 127) << 2;
                unsigned long long vh = __ldcg(
                    (const unsigned long long*)(hbh + base + (size_t)b * H_ + kk));
                unsigned long long vl = __ldcg(
                    (const unsigned long long*)(hbl + base + (size_t)b * H_ + kk));
                *(unsigned long long*)(smc + HH_OFF + (b * WROW + kk) * 2) = vh;
                *(unsigned long long*)(smc + HL_OFF + (b * WROW + kk) * 2) = vl;
            }
        }
        __syncthreads();

        // ---- tensor-core matvec: all 12 warps ----
        {
            float d0[4] = {0.f, 0.f, 0.f, 0.f};
            float d1[4] = {0.f, 0.f, 0.f, 0.f};
#pragma unroll
            for (int ps = 0; ps < 8; ++ps) {
                const unsigned pb = ps * 64;
                unsigned bh[4], bl[4], al0[4], al1[4];
                ldsm_x4(bh[0], bh[1], bh[2], bh[3], aBhi + pb);
                ldsm_x4(bl[0], bl[1], bl[2], bl[3], aBlo + pb);
                ldsm_x4(al0[0], al0[1], al0[2], al0[3], aAlo + (2 * ps) * 32);
                ldsm_x4(al1[0], al1[1], al1[2], al1[3], aAlo + (2 * ps + 1) * 32);
                const unsigned* a0 = aH[2 * ps];
                const unsigned* a1 = aH[2 * ps + 1];
                mma_bf16(d0[0], d0[1], d0[2], d0[3],
                         a0[0], a0[1], a0[2], a0[3], bh[0], bh[1]);
                mma_bf16(d0[0], d0[1], d0[2], d0[3],
                         a0[0], a0[1], a0[2], a0[3], bl[0], bl[1]);
                mma_bf16(d0[0], d0[1], d0[2], d0[3],
                         al0[0], al0[1], al0[2], al0[3], bh[0], bh[1]);
                mma_bf16(d1[0], d1[1], d1[2], d1[3],
                         a1[0], a1[1], a1[2], a1[3], bh[2], bh[3]);
                mma_bf16(d1[0], d1[1], d1[2], d1[3],
                         a1[0], a1[1], a1[2], a1[3], bl[2], bl[3]);
                mma_bf16(d1[0], d1[1], d1[2], d1[3],
                         al1[0], al1[1], al1[2], al1[3], bh[2], bh[3]);
            }
            float* rk = red + kh * 96 * 9;
            rk[(mt * 16 + fg)     * 9 + 2 * ft    ] = d0[0] + d1[0];
            rk[(mt * 16 + fg)     * 9 + 2 * ft + 1] = d0[1] + d1[1];
            rk[(mt * 16 + fg + 8) * 9 + 2 * ft    ] = d0[2] + d1[2];
            rk[(mt * 16 + fg + 8) * 9 + 2 * ft + 1] = d0[3] + d1[3];
        }
        __syncthreads();

        // ---- elementwise (threads 0-255) + early release + xp(t+1) load ----
        if (tid < 256) {
            float ghr = red[(ei) * 9 + eb]      + red[96 * 9 + (ei) * 9 + eb];
            float ghz = red[(32 + ei) * 9 + eb] + red[96 * 9 + (32 + ei) * 9 + eb];
            float ghn = red[(64 + ei) * 9 + eb] + red[96 * 9 + (64 + ei) * 9 + eb];
            ghr += sb[ei];
            ghz += sb[32 + ei];
            ghn += sb[64 + ei];

            float r = sigmoidf_(xr + ghr);
            float z = sigmoidf_(xz + ghz);
            float n = tanhf_(xn + r * ghn);
            float hnew = n + z * (h_prev_reg - n);
            h_prev_reg = hnew;

            const size_t off = ((size_t)t * B_ + rb + eb) * H_ + ibase + ei;
            unsigned hb = bf16_bits(hnew);
            float rem = hnew - bf16_val(hb);
            hbh[off] = (unsigned short)hb;
            hbl[off] = (unsigned short)bf16_bits(rem);
            if (layer) __stcg(g_h2 + off, hnew);

            asm volatile("bar.sync 1, 256;" ::: "memory");
            if (tid == 0) red_release(ctr, 1u);

            // prefetch xp for step t+1
            if (t + 1 < T_) {
                const float* xrow = xp + ((size_t)(t + 1) * B_ + rb + eb) * G3H
                                  + ibase + ei;
                xr = __ldg(xrow);
                xz = __ldg(xrow + 512);
                xn = __ldg(xrow + 1024);
            }
        }
        // MMA-only warps (8-11) proceed to next-step staging; they self-block
        // on the poll (own release above is part of the 16-count target).
    }
}

// ---------------------------------------------------------------------------
// Pool over batch + FC
// ---------------------------------------------------------------------------
__global__ __launch_bounds__(256) void pool_fc_kernel(
    const float* __restrict__ fcW, const float* __restrict__ fcb,
    float* __restrict__ out)
{
    __shared__ float rbuf[5][256];
    const int t = blockIdx.x;
    const int tid = threadIdx.x;

    float s0 = 0.f, s1 = 0.f;
    const float* base = g_h2 + (size_t)t * B_ * H_ + tid * 2;
#pragma unroll 8
    for (int b = 0; b < B_; ++b) {
        float2 vv = *(const float2*)(base + (size_t)b * H_);
        s0 += vv.x; s1 += vv.y;
    }
    s0 *= (1.0f / 64.0f);
    s1 *= (1.0f / 64.0f);

#pragma unroll
    for (int l = 0; l < L_; ++l)
        rbuf[l][tid] = s0 * __ldg(fcW + l * H_ + tid * 2)
                     + s1 * __ldg(fcW + l * H_ + tid * 2 + 1);
    __syncthreads();

    for (int s = 128; s > 0; s >>= 1) {
        if (tid < s) {
#pragma unroll
            for (int l = 0; l < L_; ++l) rbuf[l][tid] += rbuf[l][tid + s];
        }
        __syncthreads();
    }
    if (tid < L_) out[t * L_ + tid] = rbuf[tid][0] + __ldg(fcb + tid);
}

// ---------------------------------------------------------------------------
// launcher
// ---------------------------------------------------------------------------
extern "C" void kernel_launch(void* const* d_in, const int* in_sizes, int n_in,
                              void* d_out, int out_size) {
    (void)in_sizes; (void)n_in; (void)out_size;
    const int*   texts = (const int*)  d_in[0];
    const float* emb   = (const float*)d_in[1];
    const float* Wih0  = (const float*)d_in[2];
    const float* Whh0  = (const float*)d_in[3];
    const float* bih0  = (const float*)d_in[4];
    const float* bhh0  = (const float*)d_in[5];
    const float* Wih1  = (const float*)d_in[6];
    const float* Whh1  = (const float*)d_in[7];
    const float* bih1  = (const float*)d_in[8];
    const float* bhh1  = (const float*)d_in[9];
    const float* fcW   = (const float*)d_in[10];
    const float* fcb   = (const float*)d_in[11];
    float* out = (float*)d_out;

    cudaFuncSetAttribute(rec_kernel,
                         cudaFuncAttributeMaxDynamicSharedMemorySize,
                         SMEM_REC_BYTES);
    cudaFuncSetAttribute(proj_mma<EP_, 0>,
                         cudaFuncAttributeMaxDynamicSharedMemorySize, SMEM_PROJ);
    cudaFuncSetAttribute(proj_mma<H_, 1>,
                         cudaFuncAttributeMaxDynamicSharedMemorySize, SMEM_PROJ);

    init_ctr_kernel<<<1, 512>>>();
    cvt_all_kernel<<<4096, 256>>>(emb, Wih0, Wih1);
    proj_mma<EP_, 0><<<dim3(12, 256), 256, SMEM_PROJ>>>(texts, bih0);
    rec_kernel<<<128, 384, SMEM_REC_BYTES>>>(Whh0, bhh0, 0);
    proj_mma<H_, 1><<<dim3(12, 256), 256, SMEM_PROJ>>>(nullptr, bih1);
    rec_kernel<<<128, 384, SMEM_REC_BYTES>>>(Whh1, bhh1, 1);
    pool_fc_kernel<<<512, 256>>>(fcW, fcb, out);
}